// round 4
// baseline (speedup 1.0000x reference)
#include <cuda_runtime.h>
#include <cuda_fp16.h>
#include <math.h>

#define NN   100000
#define EMAX 3200000
#define FIN  256
#define CH   16
#define NL   7
#define PAD  96          // bucket capacity; P(any deg>96) ~ 1e-13 for Poisson(32)
#define GB   391         // gemm blocks = ceil(NN/256)

// ---------------- scratch (static __device__, no cudaMalloc) ----------------
// Invariant: g_deg all-zero at entry of every launch (static init covers call 1;
// k_conv2 resets it at the end of each launch).
__device__ int g_deg[NN];
__device__ __align__(128) int    g_buf[NN * PAD];   // padded adjacency (src ids by dst)
__device__ __align__(16)  __half g_h[NN * CH];      // x@W0 (unscaled, then scaled in-place)
__device__ __align__(16)  float  g_h2[NN * 8];      // dinv-scaled layer-2 input [N,8]

// ---------------- packed f32x2 helpers --------------------------------------
__device__ __forceinline__ void ffma2(unsigned long long& d,
                                      unsigned long long a, unsigned long long b) {
    asm("fma.rn.f32x2 %0, %1, %2, %0;" : "+l"(d) : "l"(a), "l"(b));
}
__device__ __forceinline__ unsigned long long pack2(float v) {
    unsigned long long r;
    asm("mov.b64 %0, {%1, %1};" : "=l"(r) : "f"(v));
    return r;
}
__device__ __forceinline__ float2 unpack2(unsigned long long v) {
    float2 r;
    asm("mov.b64 {%0, %1}, %2;" : "=f"(r.x), "=f"(r.y) : "l"(v));
    return r;
}

// ---------------- 1. fused: dense GEMM (blocks < GB) + edge scatter ---------
__global__ void k_fused(const float* __restrict__ x, const float* __restrict__ W0,
                        const int* __restrict__ src, const int* __restrict__ dst,
                        int E, int Q) {
    __shared__ __align__(16) float W0s[FIN * CH];
    int t = threadIdx.x;

    if (blockIdx.x < GB) {
        // ---- GEMM path: h[r,:] = x[r,:] @ W0 (unscaled, fp16 out) ----
        for (int i = t; i < FIN * CH; i += 256) W0s[i] = W0[i];
        __syncthreads();
        int r = blockIdx.x * 256 + t;
        if (r >= NN) return;

        const float4* xr = (const float4*)(x + (size_t)r * FIN);
        const unsigned long long* W8 = (const unsigned long long*)W0s;

        unsigned long long acc2[8];
        #pragma unroll
        for (int j = 0; j < 8; j++) acc2[j] = 0ull;

        #pragma unroll 4
        for (int i4 = 0; i4 < FIN / 4; i4++) {
            float4 v = xr[i4];
            #pragma unroll
            for (int k = 0; k < 4; k++) {
                float xv = (k == 0) ? v.x : (k == 1) ? v.y : (k == 2) ? v.z : v.w;
                unsigned long long xp = pack2(xv);
                const unsigned long long* wr = W8 + (size_t)(i4 * 4 + k) * 8;
                #pragma unroll
                for (int j = 0; j < 8; j++) ffma2(acc2[j], xp, wr[j]);
            }
        }
        __half2 hv[8];
        #pragma unroll
        for (int j = 0; j < 8; j++) {
            float2 p = unpack2(acc2[j]);
            hv[j] = __floats2half2_rn(p.x, p.y);
        }
        uint4* hr = (uint4*)(g_h + (size_t)r * CH);
        hr[0] = *(uint4*)&hv[0];
        hr[1] = *(uint4*)&hv[4];
    } else {
        // ---- fill path: 4 edges per thread, int4 loads ----
        int i = (blockIdx.x - GB) * 256 + t;
        if (i >= Q) return;
        int b = i * 4;
        if (b + 3 < E) {
            int4 s4 = ((const int4*)src)[i];
            int4 d4 = ((const int4*)dst)[i];
            int p0 = atomicAdd(&g_deg[d4.x], 1);
            if (p0 < PAD) g_buf[d4.x * PAD + p0] = s4.x;
            int p1 = atomicAdd(&g_deg[d4.y], 1);
            if (p1 < PAD) g_buf[d4.y * PAD + p1] = s4.y;
            int p2 = atomicAdd(&g_deg[d4.z], 1);
            if (p2 < PAD) g_buf[d4.z * PAD + p2] = s4.z;
            int p3 = atomicAdd(&g_deg[d4.w], 1);
            if (p3 < PAD) g_buf[d4.w * PAD + p3] = s4.w;
        } else {
            for (int j = b; j < E; j++) {
                int s = src[j], d = dst[j];
                int pos = atomicAdd(&g_deg[d], 1);
                if (pos < PAD) g_buf[d * PAD + pos] = s;
            }
        }
    }
}

// ---------------- 2. scale h rows in place by dinv[row] ---------------------
__global__ void k_scale() {
    int i = blockIdx.x * 256 + threadIdx.x;      // NN*8 half2 words
    if (i >= NN * 8) return;
    int r = i >> 3;
    float s = rsqrtf((float)(g_deg[r] + 1));     // +1 = self loop
    __half2* H = (__half2*)g_h;
    float2 v = __half22float2(H[i]);
    H[i] = __floats2half2_rn(v.x * s, v.y * s);
}

// ---------------- 3. conv1 + relu + 16->7 dense, fused ----------------------
// 8 lanes per node (4 nodes/warp). Lane j holds features 2j, 2j+1 via half2.
__global__ void k_conv1(const float* __restrict__ W1) {
    __shared__ float W1s[CH * NL];
    int t = threadIdx.x;
    if (t < CH * NL) W1s[t] = W1[t];
    __syncthreads();

    int lane = t & 31;
    int f2   = lane & 7;
    int base = lane & 24;
    int node = (blockIdx.x * blockDim.x + t) >> 3;   // exact: NN*8 % 256 == 0

    int cnt = g_deg[node];
    float dinv_d = rsqrtf((float)(cnt + 1));
    const __half2* H = (const __half2*)g_h;
    const int* adj = g_buf + (size_t)node * PAD;
    const int4* A4 = (const int4*)adj;

    float2 self = __half22float2(H[node * 8 + f2]);   // self-loop term (pre-scaled)
    float ax = self.x, ay = self.y;
    float bx = 0.f, by = 0.f, cx = 0.f, cy = 0.f, dx = 0.f, dy = 0.f;

    int n4 = cnt >> 2;
    #pragma unroll 2
    for (int q = 0; q < n4; q++) {
        int4 p = A4[q];
        float2 v0 = __half22float2(H[p.x * 8 + f2]);
        float2 v1 = __half22float2(H[p.y * 8 + f2]);
        float2 v2 = __half22float2(H[p.z * 8 + f2]);
        float2 v3 = __half22float2(H[p.w * 8 + f2]);
        ax += v0.x;  ay += v0.y;
        bx += v1.x;  by += v1.y;
        cx += v2.x;  cy += v2.y;
        dx += v3.x;  dy += v3.y;
    }
    for (int e = n4 * 4; e < cnt; e++) {
        float2 v0 = __half22float2(H[adj[e] * 8 + f2]);
        ax += v0.x;  ay += v0.y;
    }
    float rv0 = fmaxf(dinv_d * ((ax + bx) + (cx + dx)), 0.f);
    float rv1 = fmaxf(dinv_d * ((ay + by) + (cy + dy)), 0.f);

    int f  = f2;
    int jf = (f < NL) ? f : 0;
    float o = 0.f;
    #pragma unroll
    for (int j = 0; j < 8; j++) {
        float a0 = __shfl_sync(0xffffffffu, rv0, base + j);
        float a1 = __shfl_sync(0xffffffffu, rv1, base + j);
        o = fmaf(a0, W1s[(2 * j)     * NL + jf], o);
        o = fmaf(a1, W1s[(2 * j + 1) * NL + jf], o);
    }
    g_h2[node * 8 + f] = (f < NL) ? dinv_d * o : 0.f;   // pre-scaled for conv2
}

// ---------------- 4. conv2 + exp + 1; resets g_deg for next replay ----------
__global__ void k_conv2(float* __restrict__ out) {
    int t    = threadIdx.x;
    int f    = t & 7;
    int node = (blockIdx.x * blockDim.x + t) >> 3;      // exact grid

    int cnt = g_deg[node];
    const int* adj = g_buf + (size_t)node * PAD;
    const int4* A4 = (const int4*)adj;

    float a0 = g_h2[node * 8 + f];                      // self-loop term
    float a1 = 0.f, a2 = 0.f, a3 = 0.f;

    int n4 = cnt >> 2;
    #pragma unroll 2
    for (int q = 0; q < n4; q++) {
        int4 p = A4[q];
        a0 += g_h2[p.x * 8 + f];
        a1 += g_h2[p.y * 8 + f];
        a2 += g_h2[p.z * 8 + f];
        a3 += g_h2[p.w * 8 + f];
    }
    for (int e = n4 * 4; e < cnt; e++) a0 += g_h2[adj[e] * 8 + f];

    float dinv_d = rsqrtf((float)(cnt + 1));
    if (f < NL)
        out[node * NL + f] = expf(dinv_d * ((a0 + a1) + (a2 + a3))) + 1.0f;
    if (f == 7) g_deg[node] = 0;                        // self-clean for next launch
}

// ---------------- launcher ---------------------------------------------------
extern "C" void kernel_launch(void* const* d_in, const int* in_sizes, int n_in,
                              void* d_out, int out_size) {
    const float* x  = (const float*)d_in[0];   // [N,256]
    const float* W0 = (const float*)d_in[1];   // [256,16]
    const float* W1 = (const float*)d_in[2];   // [16,7]
    const int*   ei = (const int*)d_in[3];     // [2,E]
    int E = in_sizes[3] / 2;
    const int* src = ei;
    const int* dst = ei + E;
    float* out = (float*)d_out;

    int Q = (E + 3) / 4;
    int fillBlocks = (Q + 255) / 256;

    k_fused <<<GB + fillBlocks, 256>>>(x, W0, src, dst, E, Q);
    k_scale <<<(NN * 8 + 255) / 256, 256>>>();
    k_conv1 <<<(NN * 8) / 256, 256>>>(W1);
    k_conv2 <<<(NN * 8) / 256, 256>>>(out);
}

// round 5
// speedup vs baseline: 1.3003x; 1.3003x over previous
#include <cuda_runtime.h>
#include <cuda_fp16.h>
#include <math.h>

#define NN   100000
#define EMAX 3200000
#define FIN  256
#define CH   16
#define NL   7
#define PAD  96          // bucket capacity; P(any deg>96) ~ 1e-13 for Poisson(32)

// ---------------- scratch (static __device__, no cudaMalloc) ----------------
// Invariant: g_deg all-zero at entry of every launch (static init covers call 1;
// k_conv2 resets it at the end of each launch).
__device__ int g_deg[NN];
__device__ __align__(128) int    g_buf[NN * PAD];   // padded adjacency (src ids by dst)
__device__ __align__(16)  __half g_h[NN * CH];      // dinv[row]-scaled x@W0, fp16 [N,16]
__device__ __align__(16)  float  g_h2[NN * 8];      // dinv-scaled layer-2 input [N,8]

// ---------------- packed f32x2 helpers --------------------------------------
__device__ __forceinline__ void ffma2(unsigned long long& d,
                                      unsigned long long a, unsigned long long b) {
    asm("fma.rn.f32x2 %0, %1, %2, %0;" : "+l"(d) : "l"(a), "l"(b));
}
__device__ __forceinline__ unsigned long long pack2(float v) {
    unsigned long long r;
    asm("mov.b64 %0, {%1, %1};" : "=l"(r) : "f"(v));
    return r;
}
__device__ __forceinline__ float2 unpack2(unsigned long long v) {
    float2 r;
    asm("mov.b64 {%0, %1}, %2;" : "=f"(r.x), "=f"(r.y) : "l"(v));
    return r;
}

// ---------------- 1. scatter edges into padded buckets ----------------------
__global__ void k_fill(const int* __restrict__ src, const int* __restrict__ dst, int E) {
    int i = blockIdx.x * blockDim.x + threadIdx.x;
    if (i >= E) return;
    int s = src[i], d = dst[i];
    int pos = atomicAdd(&g_deg[d], 1);
    if (pos < PAD) g_buf[d * PAD + pos] = s;
}

// ---------------- 2. h = dinv[r] * (x @ W0), fp16 out, f32x2 FMA ------------
__global__ void k_gemm1(const float* __restrict__ x, const float* __restrict__ W0) {
    __shared__ __align__(16) float W0s[FIN * CH];
    int t = threadIdx.x;
    for (int i = t; i < FIN * CH; i += 256) W0s[i] = W0[i];
    __syncthreads();
    int r = blockIdx.x * 256 + t;
    if (r >= NN) return;

    const float4* xr = (const float4*)(x + (size_t)r * FIN);
    const unsigned long long* W8 = (const unsigned long long*)W0s;

    unsigned long long acc2[8];
    #pragma unroll
    for (int j = 0; j < 8; j++) acc2[j] = 0ull;

    #pragma unroll 4
    for (int i4 = 0; i4 < FIN / 4; i4++) {
        float4 v = xr[i4];
        #pragma unroll
        for (int k = 0; k < 4; k++) {
            float xv = (k == 0) ? v.x : (k == 1) ? v.y : (k == 2) ? v.z : v.w;
            unsigned long long xp = pack2(xv);
            const unsigned long long* wr = W8 + (size_t)(i4 * 4 + k) * 8;
            #pragma unroll
            for (int j = 0; j < 8; j++) ffma2(acc2[j], xp, wr[j]);
        }
    }
    float s = rsqrtf((float)(g_deg[r] + 1));     // +1 = self loop
    __half2 hv[8];
    #pragma unroll
    for (int j = 0; j < 8; j++) {
        float2 p = unpack2(acc2[j]);
        hv[j] = __floats2half2_rn(p.x * s, p.y * s);
    }
    uint4* hr = (uint4*)(g_h + (size_t)r * CH);
    hr[0] = *(uint4*)&hv[0];
    hr[1] = *(uint4*)&hv[4];
}

// ---------------- 3. conv1 + relu + 16->7 dense, fused ----------------------
// 8 lanes per node (4 nodes/warp). Lane j holds features 2j, 2j+1 via half2.
// Gather loop: 8 independent scalar adj loads + 8 gathers per iteration (MLP 8).
__global__ void k_conv1(const float* __restrict__ W1) {
    __shared__ float W1s[CH * NL];
    int t = threadIdx.x;
    if (t < CH * NL) W1s[t] = W1[t];
    __syncthreads();

    int lane = t & 31;
    int f2   = lane & 7;
    int base = lane & 24;
    int node = (blockIdx.x * blockDim.x + t) >> 3;   // exact: NN*8 % 256 == 0

    int cnt = g_deg[node];
    float dinv_d = rsqrtf((float)(cnt + 1));
    const __half2* H = (const __half2*)g_h;
    const int* adj = g_buf + (size_t)node * PAD;

    float2 self = __half22float2(H[node * 8 + f2]);   // self-loop term (pre-scaled)
    float ax0 = self.x, ay0 = self.y;
    float ax1 = 0.f, ay1 = 0.f, ax2 = 0.f, ay2 = 0.f, ax3 = 0.f, ay3 = 0.f;
    float bx0 = 0.f, by0 = 0.f, bx1 = 0.f, by1 = 0.f;
    float bx2 = 0.f, by2 = 0.f, bx3 = 0.f, by3 = 0.f;

    int e = 0;
    for (; e + 7 < cnt; e += 8) {
        int s0 = adj[e];     int s1 = adj[e + 1];
        int s2 = adj[e + 2]; int s3 = adj[e + 3];
        int s4 = adj[e + 4]; int s5 = adj[e + 5];
        int s6 = adj[e + 6]; int s7 = adj[e + 7];
        float2 v0 = __half22float2(H[s0 * 8 + f2]);
        float2 v1 = __half22float2(H[s1 * 8 + f2]);
        float2 v2 = __half22float2(H[s2 * 8 + f2]);
        float2 v3 = __half22float2(H[s3 * 8 + f2]);
        float2 v4 = __half22float2(H[s4 * 8 + f2]);
        float2 v5 = __half22float2(H[s5 * 8 + f2]);
        float2 v6 = __half22float2(H[s6 * 8 + f2]);
        float2 v7 = __half22float2(H[s7 * 8 + f2]);
        ax0 += v0.x; ay0 += v0.y;  ax1 += v1.x; ay1 += v1.y;
        ax2 += v2.x; ay2 += v2.y;  ax3 += v3.x; ay3 += v3.y;
        bx0 += v4.x; by0 += v4.y;  bx1 += v5.x; by1 += v5.y;
        bx2 += v6.x; by2 += v6.y;  bx3 += v7.x; by3 += v7.y;
    }
    for (; e < cnt; e++) {
        float2 v0 = __half22float2(H[adj[e] * 8 + f2]);
        ax0 += v0.x;  ay0 += v0.y;
    }
    float sx = ((ax0 + ax1) + (ax2 + ax3)) + ((bx0 + bx1) + (bx2 + bx3));
    float sy = ((ay0 + ay1) + (ay2 + ay3)) + ((by0 + by1) + (by2 + by3));
    float rv0 = fmaxf(dinv_d * sx, 0.f);
    float rv1 = fmaxf(dinv_d * sy, 0.f);

    int f  = f2;
    int jf = (f < NL) ? f : 0;
    float o = 0.f;
    #pragma unroll
    for (int j = 0; j < 8; j++) {
        float a0 = __shfl_sync(0xffffffffu, rv0, base + j);
        float a1 = __shfl_sync(0xffffffffu, rv1, base + j);
        o = fmaf(a0, W1s[(2 * j)     * NL + jf], o);
        o = fmaf(a1, W1s[(2 * j + 1) * NL + jf], o);
    }
    g_h2[node * 8 + f] = (f < NL) ? dinv_d * o : 0.f;   // pre-scaled for conv2
}

// ---------------- 4. conv2 + exp + 1; resets g_deg for next replay ----------
__global__ void k_conv2(float* __restrict__ out) {
    int t    = threadIdx.x;
    int f    = t & 7;
    int node = (blockIdx.x * blockDim.x + t) >> 3;      // exact grid

    int cnt = g_deg[node];
    const int* adj = g_buf + (size_t)node * PAD;

    float a0 = g_h2[node * 8 + f];                      // self-loop term
    float a1 = 0.f, a2 = 0.f, a3 = 0.f;
    float a4 = 0.f, a5 = 0.f, a6 = 0.f, a7 = 0.f;
    int e = 0;
    for (; e + 7 < cnt; e += 8) {
        int s0 = adj[e];     int s1 = adj[e + 1];
        int s2 = adj[e + 2]; int s3 = adj[e + 3];
        int s4 = adj[e + 4]; int s5 = adj[e + 5];
        int s6 = adj[e + 6]; int s7 = adj[e + 7];
        a0 += g_h2[s0 * 8 + f];
        a1 += g_h2[s1 * 8 + f];
        a2 += g_h2[s2 * 8 + f];
        a3 += g_h2[s3 * 8 + f];
        a4 += g_h2[s4 * 8 + f];
        a5 += g_h2[s5 * 8 + f];
        a6 += g_h2[s6 * 8 + f];
        a7 += g_h2[s7 * 8 + f];
    }
    for (; e < cnt; e++) a0 += g_h2[adj[e] * 8 + f];

    float dinv_d = rsqrtf((float)(cnt + 1));
    if (f < NL)
        out[node * NL + f] = expf(dinv_d * (((a0 + a1) + (a2 + a3)) +
                                            ((a4 + a5) + (a6 + a7)))) + 1.0f;
    if (f == 7) g_deg[node] = 0;                        // self-clean for next launch
}

// ---------------- launcher ---------------------------------------------------
extern "C" void kernel_launch(void* const* d_in, const int* in_sizes, int n_in,
                              void* d_out, int out_size) {
    const float* x  = (const float*)d_in[0];   // [N,256]
    const float* W0 = (const float*)d_in[1];   // [256,16]
    const float* W1 = (const float*)d_in[2];   // [16,7]
    const int*   ei = (const int*)d_in[3];     // [2,E]
    int E = in_sizes[3] / 2;
    const int* src = ei;
    const int* dst = ei + E;
    float* out = (float*)d_out;

    k_fill  <<<(E + 255) / 256, 256>>>(src, dst, E);
    k_gemm1 <<<(NN + 255) / 256, 256>>>(x, W0);
    k_conv1 <<<(NN * 8) / 256, 256>>>(W1);
    k_conv2 <<<(NN * 8) / 256, 256>>>(out);
}

// round 6
// speedup vs baseline: 1.3242x; 1.0184x over previous
#include <cuda_runtime.h>
#include <cuda_fp16.h>
#include <math.h>

#define NN   100000
#define EMAX 3200000
#define FIN  256
#define CH   16
#define NL   7
#define PAD  96          // bucket capacity; P(any deg>96) ~ 1e-13 for Poisson(32)

// ---------------- scratch (static __device__, no cudaMalloc) ----------------
// Invariant: g_deg all-zero at entry of every launch (static init covers call 1;
// k_conv2 resets it at the end of each launch).
__device__ int g_deg[NN];
__device__ __align__(128) int    g_buf[NN * PAD];   // padded adjacency (src ids by dst)
__device__ __align__(16)  __half g_h[NN * CH];      // dinv[row]-scaled x@W0, fp16 [N,16]
__device__ __align__(16)  float  g_h2[NN * 8];      // dinv-scaled layer-2 input [N,8]

// ---------------- packed f32x2 helpers --------------------------------------
__device__ __forceinline__ void ffma2(unsigned long long& d,
                                      unsigned long long a, unsigned long long b) {
    asm("fma.rn.f32x2 %0, %1, %2, %0;" : "+l"(d) : "l"(a), "l"(b));
}
__device__ __forceinline__ unsigned long long pack2(float v) {
    unsigned long long r;
    asm("mov.b64 %0, {%1, %1};" : "=l"(r) : "f"(v));
    return r;
}
__device__ __forceinline__ float2 unpack2(unsigned long long v) {
    float2 r;
    asm("mov.b64 {%0, %1}, %2;" : "=f"(r.x), "=f"(r.y) : "l"(v));
    return r;
}

// ---------------- 1. scatter edges into padded buckets ----------------------
__global__ void k_fill(const int* __restrict__ src, const int* __restrict__ dst, int E) {
    int i = blockIdx.x * blockDim.x + threadIdx.x;
    if (i >= E) return;
    int s = src[i], d = dst[i];
    int pos = atomicAdd(&g_deg[d], 1);
    if (pos < PAD) g_buf[d * PAD + pos] = s;
}

// ---------------- 2. h = dinv[r] * (x @ W0), fp16 out, f32x2 FMA ------------
__global__ void k_gemm1(const float* __restrict__ x, const float* __restrict__ W0) {
    __shared__ __align__(16) float W0s[FIN * CH];
    int t = threadIdx.x;
    for (int i = t; i < FIN * CH; i += 256) W0s[i] = W0[i];
    __syncthreads();
    int r = blockIdx.x * 256 + t;
    if (r >= NN) return;

    const float4* xr = (const float4*)(x + (size_t)r * FIN);
    const unsigned long long* W8 = (const unsigned long long*)W0s;

    unsigned long long acc2[8];
    #pragma unroll
    for (int j = 0; j < 8; j++) acc2[j] = 0ull;

    #pragma unroll 4
    for (int i4 = 0; i4 < FIN / 4; i4++) {
        float4 v = xr[i4];
        #pragma unroll
        for (int k = 0; k < 4; k++) {
            float xv = (k == 0) ? v.x : (k == 1) ? v.y : (k == 2) ? v.z : v.w;
            unsigned long long xp = pack2(xv);
            const unsigned long long* wr = W8 + (size_t)(i4 * 4 + k) * 8;
            #pragma unroll
            for (int j = 0; j < 8; j++) ffma2(acc2[j], xp, wr[j]);
        }
    }
    float s = rsqrtf((float)(g_deg[r] + 1));     // +1 = self loop
    __half2 hv[8];
    #pragma unroll
    for (int j = 0; j < 8; j++) {
        float2 p = unpack2(acc2[j]);
        hv[j] = __floats2half2_rn(p.x * s, p.y * s);
    }
    uint4* hr = (uint4*)(g_h + (size_t)r * CH);
    hr[0] = *(uint4*)&hv[0];
    hr[1] = *(uint4*)&hv[4];
}

// ---------------- 3. conv1 + relu + 16->7 dense, fused ----------------------
// 8 lanes per node (4 nodes/warp). Lane j holds features 2j, 2j+1 via half2.
// Adjacency read cooperatively: lane f loads adj[e+f] (1 sector / 8 edges),
// src ids distributed via group-masked shuffles.
__global__ void k_conv1(const float* __restrict__ W1) {
    __shared__ float W1s[CH * NL];
    int t = threadIdx.x;
    if (t < CH * NL) W1s[t] = W1[t];
    __syncthreads();

    int lane = t & 31;
    int f2   = lane & 7;
    int base = lane & 24;
    unsigned gmask = 0xFFu << base;                   // 8-lane group mask
    int node = (blockIdx.x * blockDim.x + t) >> 3;    // exact: NN*8 % 256 == 0

    int cnt = g_deg[node];
    float dinv_d = rsqrtf((float)(cnt + 1));
    const __half2* H = (const __half2*)g_h;
    const int* adj = g_buf + (size_t)node * PAD;

    float2 self = __half22float2(H[node * 8 + f2]);   // self-loop term (pre-scaled)
    float ax0 = self.x, ay0 = self.y;
    float ax1 = 0.f, ay1 = 0.f, ax2 = 0.f, ay2 = 0.f, ax3 = 0.f, ay3 = 0.f;
    float bx0 = 0.f, by0 = 0.f, bx1 = 0.f, by1 = 0.f;
    float bx2 = 0.f, by2 = 0.f, bx3 = 0.f, by3 = 0.f;

    int n8 = cnt & ~7;
    int e = 0;
    for (; e < n8; e += 8) {
        int my = __ldg(&adj[e + f2]);                 // coalesced: 32B per group
        int s0 = __shfl_sync(gmask, my, base + 0);
        int s1 = __shfl_sync(gmask, my, base + 1);
        int s2 = __shfl_sync(gmask, my, base + 2);
        int s3 = __shfl_sync(gmask, my, base + 3);
        int s4 = __shfl_sync(gmask, my, base + 4);
        int s5 = __shfl_sync(gmask, my, base + 5);
        int s6 = __shfl_sync(gmask, my, base + 6);
        int s7 = __shfl_sync(gmask, my, base + 7);
        float2 v0 = __half22float2(H[s0 * 8 + f2]);
        float2 v1 = __half22float2(H[s1 * 8 + f2]);
        float2 v2 = __half22float2(H[s2 * 8 + f2]);
        float2 v3 = __half22float2(H[s3 * 8 + f2]);
        float2 v4 = __half22float2(H[s4 * 8 + f2]);
        float2 v5 = __half22float2(H[s5 * 8 + f2]);
        float2 v6 = __half22float2(H[s6 * 8 + f2]);
        float2 v7 = __half22float2(H[s7 * 8 + f2]);
        ax0 += v0.x; ay0 += v0.y;  ax1 += v1.x; ay1 += v1.y;
        ax2 += v2.x; ay2 += v2.y;  ax3 += v3.x; ay3 += v3.y;
        bx0 += v4.x; by0 += v4.y;  bx1 += v5.x; by1 += v5.y;
        bx2 += v6.x; by2 += v6.y;  bx3 += v7.x; by3 += v7.y;
    }
    if (e < cnt) {                                    // tail chunk, predicated adds
        int rem = cnt - e;                            // 1..7
        int my = __ldg(&adj[e + f2]);                 // in-bounds (e+7 <= 95)
        #pragma unroll
        for (int j = 0; j < 7; j++) {
            int sj = __shfl_sync(gmask, my, base + j);
            if (j < rem) {
                float2 v = __half22float2(H[sj * 8 + f2]);
                ax0 += v.x;  ay0 += v.y;
            }
        }
    }
    float sx = ((ax0 + ax1) + (ax2 + ax3)) + ((bx0 + bx1) + (bx2 + bx3));
    float sy = ((ay0 + ay1) + (ay2 + ay3)) + ((by0 + by1) + (by2 + by3));
    float rv0 = fmaxf(dinv_d * sx, 0.f);
    float rv1 = fmaxf(dinv_d * sy, 0.f);

    int f  = f2;
    int jf = (f < NL) ? f : 0;
    float o = 0.f;
    #pragma unroll
    for (int j = 0; j < 8; j++) {
        float a0 = __shfl_sync(0xffffffffu, rv0, base + j);
        float a1 = __shfl_sync(0xffffffffu, rv1, base + j);
        o = fmaf(a0, W1s[(2 * j)     * NL + jf], o);
        o = fmaf(a1, W1s[(2 * j + 1) * NL + jf], o);
    }
    g_h2[node * 8 + f] = (f < NL) ? dinv_d * o : 0.f;   // pre-scaled for conv2
}

// ---------------- 4. conv2 + exp + 1; resets g_deg for next replay ----------
__global__ void k_conv2(float* __restrict__ out) {
    int t    = threadIdx.x;
    int lane = t & 31;
    int f    = lane & 7;
    int base = lane & 24;
    unsigned gmask = 0xFFu << base;
    int node = (blockIdx.x * blockDim.x + t) >> 3;      // exact grid

    int cnt = g_deg[node];
    const int* adj = g_buf + (size_t)node * PAD;

    float a0 = g_h2[node * 8 + f];                      // self-loop term
    float a1 = 0.f, a2 = 0.f, a3 = 0.f;
    float a4 = 0.f, a5 = 0.f, a6 = 0.f, a7 = 0.f;

    int n8 = cnt & ~7;
    int e = 0;
    for (; e < n8; e += 8) {
        int my = __ldg(&adj[e + f]);
        int s0 = __shfl_sync(gmask, my, base + 0);
        int s1 = __shfl_sync(gmask, my, base + 1);
        int s2 = __shfl_sync(gmask, my, base + 2);
        int s3 = __shfl_sync(gmask, my, base + 3);
        int s4 = __shfl_sync(gmask, my, base + 4);
        int s5 = __shfl_sync(gmask, my, base + 5);
        int s6 = __shfl_sync(gmask, my, base + 6);
        int s7 = __shfl_sync(gmask, my, base + 7);
        a0 += g_h2[s0 * 8 + f];
        a1 += g_h2[s1 * 8 + f];
        a2 += g_h2[s2 * 8 + f];
        a3 += g_h2[s3 * 8 + f];
        a4 += g_h2[s4 * 8 + f];
        a5 += g_h2[s5 * 8 + f];
        a6 += g_h2[s6 * 8 + f];
        a7 += g_h2[s7 * 8 + f];
    }
    if (e < cnt) {
        int rem = cnt - e;                              // 1..7
        int my = __ldg(&adj[e + f]);
        #pragma unroll
        for (int j = 0; j < 7; j++) {
            int sj = __shfl_sync(gmask, my, base + j);
            if (j < rem) a0 += g_h2[sj * 8 + f];
        }
    }

    float dinv_d = rsqrtf((float)(cnt + 1));
    if (f < NL)
        out[node * NL + f] = expf(dinv_d * (((a0 + a1) + (a2 + a3)) +
                                            ((a4 + a5) + (a6 + a7)))) + 1.0f;
    if (f == 7) g_deg[node] = 0;                        // self-clean for next launch
}

// ---------------- launcher ---------------------------------------------------
extern "C" void kernel_launch(void* const* d_in, const int* in_sizes, int n_in,
                              void* d_out, int out_size) {
    const float* x  = (const float*)d_in[0];   // [N,256]
    const float* W0 = (const float*)d_in[1];   // [256,16]
    const float* W1 = (const float*)d_in[2];   // [16,7]
    const int*   ei = (const int*)d_in[3];     // [2,E]
    int E = in_sizes[3] / 2;
    const int* src = ei;
    const int* dst = ei + E;
    float* out = (float*)d_out;

    k_fill  <<<(E + 255) / 256, 256>>>(src, dst, E);
    k_gemm1 <<<(NN + 255) / 256, 256>>>(x, W0);
    k_conv1 <<<(NN * 8) / 256, 256>>>(W1);
    k_conv2 <<<(NN * 8) / 256, 256>>>(out);
}

// round 7
// speedup vs baseline: 1.5046x; 1.1362x over previous
#include <cuda_runtime.h>
#include <cuda_fp16.h>
#include <math.h>

#define NN   100000
#define EMAX 3200000
#define FIN  256
#define CH   16
#define NL   7
#define PAD  96          // bucket capacity; P(any deg>96) ~ 1e-13 for Poisson(32)

// ---------------- scratch (static __device__, no cudaMalloc) ----------------
// Invariant: g_deg all-zero at entry of every launch (static init covers call 1;
// k_conv2 resets it at the end of each launch).
__device__ int g_deg[NN];
__device__ __align__(128) int    g_buf[NN * PAD];   // padded adjacency (src ids by dst)
__device__ __align__(16)  __half g_h[NN * CH];      // x@W0 fp16 (unscaled, then scaled in place)
__device__ __align__(16)  __half g_h2[NN * 8];      // dinv-scaled layer-2 input, fp16 [N,8]

// ---------------- packed f32x2 helpers --------------------------------------
__device__ __forceinline__ void ffma2(unsigned long long& d,
                                      unsigned long long a, unsigned long long b) {
    asm("fma.rn.f32x2 %0, %1, %2, %0;" : "+l"(d) : "l"(a), "l"(b));
}
__device__ __forceinline__ unsigned long long pack2(float v) {
    unsigned long long r;
    asm("mov.b64 %0, {%1, %1};" : "=l"(r) : "f"(v));
    return r;
}
__device__ __forceinline__ float2 unpack2(unsigned long long v) {
    float2 r;
    asm("mov.b64 {%0, %1}, %2;" : "=f"(r.x), "=f"(r.y) : "l"(v));
    return r;
}

// ---------------- 1. scatter edges into padded buckets (4 edges/thread) -----
__global__ void k_fill(const int* __restrict__ src, const int* __restrict__ dst,
                       int E, int Q) {
    int i = blockIdx.x * blockDim.x + threadIdx.x;
    if (i >= Q) return;
    #pragma unroll
    for (int k = 0; k < 4; k++) {
        int j = i + k * Q;                        // coalesced strided access
        if (j < E) {
            int s = src[j], d = dst[j];
            int pos = atomicAdd(&g_deg[d], 1);
            if (pos < PAD) g_buf[d * PAD + pos] = s;
        }
    }
}

// ---------------- 2. h = x @ W0 (UNSCALED), fp16 out, f32x2 FMA -------------
// Runs concurrently with k_fill (does not touch g_deg).
__global__ void k_gemm1(const float* __restrict__ x, const float* __restrict__ W0) {
    __shared__ __align__(16) float W0s[FIN * CH];
    int t = threadIdx.x;
    for (int i = t; i < FIN * CH; i += 256) W0s[i] = W0[i];
    __syncthreads();
    int r = blockIdx.x * 256 + t;
    if (r >= NN) return;

    const float4* xr = (const float4*)(x + (size_t)r * FIN);
    const unsigned long long* W8 = (const unsigned long long*)W0s;

    unsigned long long acc2[8];
    #pragma unroll
    for (int j = 0; j < 8; j++) acc2[j] = 0ull;

    #pragma unroll 4
    for (int i4 = 0; i4 < FIN / 4; i4++) {
        float4 v = xr[i4];
        #pragma unroll
        for (int k = 0; k < 4; k++) {
            float xv = (k == 0) ? v.x : (k == 1) ? v.y : (k == 2) ? v.z : v.w;
            unsigned long long xp = pack2(xv);
            const unsigned long long* wr = W8 + (size_t)(i4 * 4 + k) * 8;
            #pragma unroll
            for (int j = 0; j < 8; j++) ffma2(acc2[j], xp, wr[j]);
        }
    }
    __half2 hv[8];
    #pragma unroll
    for (int j = 0; j < 8; j++) {
        float2 p = unpack2(acc2[j]);
        hv[j] = __floats2half2_rn(p.x, p.y);
    }
    uint4* hr = (uint4*)(g_h + (size_t)r * CH);
    hr[0] = *(uint4*)&hv[0];
    hr[1] = *(uint4*)&hv[4];
}

// ---------------- 3. scale h rows in place by dinv[row] ---------------------
__global__ void k_scale() {
    int i = blockIdx.x * 256 + threadIdx.x;      // NN*8 half2 words
    if (i >= NN * 8) return;
    int r = i >> 3;
    float s = rsqrtf((float)(g_deg[r] + 1));     // +1 = self loop
    __half2* H = (__half2*)g_h;
    float2 v = __half22float2(H[i]);
    H[i] = __floats2half2_rn(v.x * s, v.y * s);
}

// ---------------- 4. conv1 + relu + 16->7 dense, fused ----------------------
// 8 lanes per node (4 nodes/warp). Lane j holds features 2j, 2j+1 via half2.
// Adjacency read cooperatively (1 sector / 8 edges) + group shuffles.
__global__ void k_conv1(const float* __restrict__ W1) {
    __shared__ float W1s[CH * NL];
    int t = threadIdx.x;
    if (t < CH * NL) W1s[t] = W1[t];
    __syncthreads();

    int lane = t & 31;
    int f2   = lane & 7;
    int base = lane & 24;
    unsigned gmask = 0xFFu << base;                   // 8-lane group mask
    int node = (blockIdx.x * blockDim.x + t) >> 3;    // exact: NN*8 % 256 == 0

    int cnt = g_deg[node];
    float dinv_d = rsqrtf((float)(cnt + 1));
    const __half2* H = (const __half2*)g_h;
    const int* adj = g_buf + (size_t)node * PAD;

    float2 self = __half22float2(H[node * 8 + f2]);   // self-loop term (pre-scaled)
    float ax0 = self.x, ay0 = self.y;
    float ax1 = 0.f, ay1 = 0.f, ax2 = 0.f, ay2 = 0.f, ax3 = 0.f, ay3 = 0.f;
    float bx0 = 0.f, by0 = 0.f, bx1 = 0.f, by1 = 0.f;
    float bx2 = 0.f, by2 = 0.f, bx3 = 0.f, by3 = 0.f;

    int n8 = cnt & ~7;
    int e = 0;
    for (; e < n8; e += 8) {
        int my = __ldg(&adj[e + f2]);                 // coalesced: 32B per group
        int s0 = __shfl_sync(gmask, my, base + 0);
        int s1 = __shfl_sync(gmask, my, base + 1);
        int s2 = __shfl_sync(gmask, my, base + 2);
        int s3 = __shfl_sync(gmask, my, base + 3);
        int s4 = __shfl_sync(gmask, my, base + 4);
        int s5 = __shfl_sync(gmask, my, base + 5);
        int s6 = __shfl_sync(gmask, my, base + 6);
        int s7 = __shfl_sync(gmask, my, base + 7);
        float2 v0 = __half22float2(H[s0 * 8 + f2]);
        float2 v1 = __half22float2(H[s1 * 8 + f2]);
        float2 v2 = __half22float2(H[s2 * 8 + f2]);
        float2 v3 = __half22float2(H[s3 * 8 + f2]);
        float2 v4 = __half22float2(H[s4 * 8 + f2]);
        float2 v5 = __half22float2(H[s5 * 8 + f2]);
        float2 v6 = __half22float2(H[s6 * 8 + f2]);
        float2 v7 = __half22float2(H[s7 * 8 + f2]);
        ax0 += v0.x; ay0 += v0.y;  ax1 += v1.x; ay1 += v1.y;
        ax2 += v2.x; ay2 += v2.y;  ax3 += v3.x; ay3 += v3.y;
        bx0 += v4.x; by0 += v4.y;  bx1 += v5.x; by1 += v5.y;
        bx2 += v6.x; by2 += v6.y;  bx3 += v7.x; by3 += v7.y;
    }
    if (e < cnt) {                                    // tail chunk, predicated adds
        int rem = cnt - e;                            // 1..7
        int my = __ldg(&adj[e + f2]);                 // in-bounds (e+7 <= 95)
        #pragma unroll
        for (int j = 0; j < 7; j++) {
            int sj = __shfl_sync(gmask, my, base + j);
            if (j < rem) {
                float2 v = __half22float2(H[sj * 8 + f2]);
                ax0 += v.x;  ay0 += v.y;
            }
        }
    }
    float sx = ((ax0 + ax1) + (ax2 + ax3)) + ((bx0 + bx1) + (bx2 + bx3));
    float sy = ((ay0 + ay1) + (ay2 + ay3)) + ((by0 + by1) + (by2 + by3));
    float rv0 = fmaxf(dinv_d * sx, 0.f);
    float rv1 = fmaxf(dinv_d * sy, 0.f);

    int f  = f2;
    int jf = (f < NL) ? f : 0;
    float o = 0.f;
    #pragma unroll
    for (int j = 0; j < 8; j++) {
        float a0 = __shfl_sync(0xffffffffu, rv0, base + j);
        float a1 = __shfl_sync(0xffffffffu, rv1, base + j);
        o = fmaf(a0, W1s[(2 * j)     * NL + jf], o);
        o = fmaf(a1, W1s[(2 * j + 1) * NL + jf], o);
    }
    g_h2[node * 8 + f] = __float2half((f < NL) ? dinv_d * o : 0.f);  // fp16, pre-scaled
}

// ---------------- 5. conv2 + exp + 1; resets g_deg for next replay ----------
__global__ void k_conv2(float* __restrict__ out) {
    int t    = threadIdx.x;
    int lane = t & 31;
    int f    = lane & 7;
    int base = lane & 24;
    unsigned gmask = 0xFFu << base;
    int node = (blockIdx.x * blockDim.x + t) >> 3;      // exact grid

    int cnt = g_deg[node];
    const int* adj = g_buf + (size_t)node * PAD;
    const __half* H2 = g_h2;

    float a0 = __half2float(H2[node * 8 + f]);          // self-loop term
    float a1 = 0.f, a2 = 0.f, a3 = 0.f;
    float a4 = 0.f, a5 = 0.f, a6 = 0.f, a7 = 0.f;

    int n8 = cnt & ~7;
    int e = 0;
    for (; e < n8; e += 8) {
        int my = __ldg(&adj[e + f]);
        int s0 = __shfl_sync(gmask, my, base + 0);
        int s1 = __shfl_sync(gmask, my, base + 1);
        int s2 = __shfl_sync(gmask, my, base + 2);
        int s3 = __shfl_sync(gmask, my, base + 3);
        int s4 = __shfl_sync(gmask, my, base + 4);
        int s5 = __shfl_sync(gmask, my, base + 5);
        int s6 = __shfl_sync(gmask, my, base + 6);
        int s7 = __shfl_sync(gmask, my, base + 7);
        a0 += __half2float(H2[s0 * 8 + f]);
        a1 += __half2float(H2[s1 * 8 + f]);
        a2 += __half2float(H2[s2 * 8 + f]);
        a3 += __half2float(H2[s3 * 8 + f]);
        a4 += __half2float(H2[s4 * 8 + f]);
        a5 += __half2float(H2[s5 * 8 + f]);
        a6 += __half2float(H2[s6 * 8 + f]);
        a7 += __half2float(H2[s7 * 8 + f]);
    }
    if (e < cnt) {
        int rem = cnt - e;                              // 1..7
        int my = __ldg(&adj[e + f]);
        #pragma unroll
        for (int j = 0; j < 7; j++) {
            int sj = __shfl_sync(gmask, my, base + j);
            if (j < rem) a0 += __half2float(H2[sj * 8 + f]);
        }
    }

    float dinv_d = rsqrtf((float)(cnt + 1));
    if (f < NL)
        out[node * NL + f] = expf(dinv_d * (((a0 + a1) + (a2 + a3)) +
                                            ((a4 + a5) + (a6 + a7)))) + 1.0f;
    if (f == 7) g_deg[node] = 0;                        // self-clean for next launch
}

// ---------------- launcher ---------------------------------------------------
extern "C" void kernel_launch(void* const* d_in, const int* in_sizes, int n_in,
                              void* d_out, int out_size) {
    const float* x  = (const float*)d_in[0];   // [N,256]
    const float* W0 = (const float*)d_in[1];   // [256,16]
    const float* W1 = (const float*)d_in[2];   // [16,7]
    const int*   ei = (const int*)d_in[3];     // [2,E]
    int E = in_sizes[3] / 2;
    const int* src = ei;
    const int* dst = ei + E;
    float* out = (float*)d_out;

    // Lazily created side stream + events for a fork-join inside graph capture.
    // (Host-side objects only — no device memory. Same work every call.)
    static cudaStream_t s2 = nullptr;
    static cudaEvent_t evFork = nullptr, evJoin = nullptr;
    if (s2 == nullptr) {
        cudaStreamCreateWithFlags(&s2, cudaStreamNonBlocking);
        cudaEventCreateWithFlags(&evFork, cudaEventDisableTiming);
        cudaEventCreateWithFlags(&evJoin, cudaEventDisableTiming);
    }

    int Q = (E + 3) / 4;

    // fork: gemm1 (unscaled, independent of g_deg) runs concurrently with fill
    cudaEventRecord(evFork, 0);
    cudaStreamWaitEvent(s2, evFork, 0);
    k_gemm1 <<<(NN + 255) / 256, 256, 0, s2>>>(x, W0);
    k_fill  <<<(Q + 255) / 256, 256>>>(src, dst, E, Q);
    cudaEventRecord(evJoin, s2);
    cudaStreamWaitEvent(0, evJoin, 0);
    // join: everything below depends on both branches
    k_scale <<<(NN * 8 + 255) / 256, 256>>>();
    k_conv1 <<<(NN * 8) / 256, 256>>>(W1);
    k_conv2 <<<(NN * 8) / 256, 256>>>(out);
}